// round 14
// baseline (speedup 1.0000x reference)
#include <cuda_runtime.h>
#include <cuda_bf16.h>
#include <math.h>
#include <stdint.h>

// ---------------- problem constants ----------------
#define BB      4
#define NH      16
#define NKV     4
#define HDIM    128
#define DMODEL  2048
#define SQV     1024
#define SQA     64
#define SCACHE  256
#define STOT    1344
#define NQROWS  (BB*NH*SQA)

// ---------------- fp32 scratch ----------------
__device__ float g_K[BB*NKV*STOT*HDIM];
__device__ float g_V[BB*NKV*STOT*HDIM];
__device__ float g_q[BB*NH*SQA*HDIM];
__device__ float g_scores[NQROWS*STOT];
__device__ float g_attn[BB*SQA*NH*HDIM];

// ---------------- bf16 split operands (hi + lo) ----------------
__device__ __nv_bfloat16 g_hv_hi[4096*2048], g_hv_lo[4096*2048];
__device__ __nv_bfloat16 g_ha_hi[256*2048],  g_ha_lo[256*2048];
__device__ __nv_bfloat16 g_at_hi[256*2048],  g_at_lo[256*2048];
__device__ __nv_bfloat16 g_wkv_hi[512*2048], g_wkv_lo[512*2048];
__device__ __nv_bfloat16 g_wvv_hi[512*2048], g_wvv_lo[512*2048];
__device__ __nv_bfloat16 g_wq_hi[2048*2048], g_wq_lo[2048*2048];
__device__ __nv_bfloat16 g_wka_hi[512*2048], g_wka_lo[512*2048];
__device__ __nv_bfloat16 g_wva_hi[512*2048], g_wva_lo[512*2048];
__device__ __nv_bfloat16 g_wo_hi[2048*2048], g_wo_lo[2048*2048];

// attention bf16 operands
__device__ __nv_bfloat16 g_qh[BB*NH*SQA*HDIM],  g_ql[BB*NH*SQA*HDIM];
__device__ __nv_bfloat16 g_Kh[BB*NKV*STOT*HDIM], g_Kl[BB*NKV*STOT*HDIM];
__device__ __nv_bfloat16 g_Vth[BB*NKV*HDIM*STOT], g_Vtl[BB*NKV*HDIM*STOT];
__device__ __nv_bfloat16 g_Ph[NQROWS*STOT], g_Pl[NQROWS*STOT];

// ================= PTX helpers =================
__device__ __forceinline__ uint32_t smem_to_u32(const void* p) {
    uint32_t a;
    asm("{ .reg .u64 t; cvta.to.shared.u64 t, %1; cvt.u32.u64 %0, t; }" : "=r"(a) : "l"(p));
    return a;
}
#define CP_ASYNC16(sm, gm) \
    asm volatile("cp.async.cg.shared.global [%0], [%1], 16;" :: "r"(sm), "l"(gm))
#define CP_COMMIT() asm volatile("cp.async.commit_group;" ::: "memory")
#define CP_WAIT(n)  asm volatile("cp.async.wait_group %0;" :: "n"(n) : "memory")

__device__ __forceinline__ void ldsm_x4(uint32_t* r, uint32_t addr) {
    asm volatile("ldmatrix.sync.aligned.m8n8.x4.shared.b16 {%0,%1,%2,%3}, [%4];"
        : "=r"(r[0]), "=r"(r[1]), "=r"(r[2]), "=r"(r[3]) : "r"(addr));
}
__device__ __forceinline__ void mma_bf16(float* d, const uint32_t* a, const uint32_t* b) {
    asm volatile("mma.sync.aligned.m16n8k16.row.col.f32.bf16.bf16.f32 "
        "{%0,%1,%2,%3}, {%4,%5,%6,%7}, {%8,%9}, {%0,%1,%2,%3};"
        : "+f"(d[0]), "+f"(d[1]), "+f"(d[2]), "+f"(d[3])
        : "r"(a[0]), "r"(a[1]), "r"(a[2]), "r"(a[3]), "r"(b[0]), "r"(b[1]));
}
__device__ __forceinline__ uint32_t swz(uint32_t off) { return off ^ ((off >> 3) & 0x70); }

__device__ __forceinline__ void split_bf16(float v, __nv_bfloat16& h, __nv_bfloat16& l) {
    h = __float2bfloat16(v);
    l = __float2bfloat16(v - __bfloat162float(h));
}

// ---------------- output index mapping ----------------
__device__ __forceinline__ int out_index(int map, int r, int c, int N) {
    switch (map) {
        case 1: { int b=r>>10, s=r&1023, kv=c>>7, d=c&127;
                  return (((b*NKV+kv)*STOT) + SCACHE + s)*HDIM + d; }
        case 2: { int b=r>>6, s=r&63, kv=c>>7, d=c&127;
                  return (((b*NKV+kv)*STOT) + (SCACHE+SQV) + s)*HDIM + d; }
        case 3: { int b=r>>6, s=r&63, h=c>>7, d=c&127;
                  return (((b*NH+h)*SQA) + s)*HDIM + d; }
        default: return r*N + c;
    }
}

// ---------------- merged projection GEMM (validated round 12) ----------------
#define TCG_SMEM_BYTES (98304)
__global__ void __launch_bounds__(256, 2) tc_proj()
{
    extern __shared__ char smem[];
    uint32_t sbase = smem_to_u32(smem);

    const int tid = threadIdx.x, lane = tid & 31, wid = tid >> 5;
    const int wm = wid & 1, wn = wid >> 1;

    int bid = blockIdx.x;
    const __nv_bfloat16 *Ahi, *Alo, *Bh, *Bl;
    int m0, n0, kstart, nch, map, dest, Nl;
    bool split;
    const int K = 2048;

    if (bid < 512) {
        int n = bid & 7, m = bid >> 3;
        m0 = m * 64; kstart = 0; nch = 32; split = false;
        Ahi = g_hv_hi; Alo = g_hv_lo;
        int n0g = n * 128;
        if (n0g < 512) { Bh = g_wkv_hi; Bl = g_wkv_lo; n0 = n0g;       map = 1; dest = 0; Nl = 512; }
        else           { Bh = g_wvv_hi; Bl = g_wvv_lo; n0 = n0g - 512; map = 1; dest = 1; Nl = 512; }
    } else {
        int l = bid - 512;
        int n = l % 24; l /= 24;
        int m = l & 3;  int z = l >> 2;
        m0 = m * 64; kstart = z * 512; nch = 8; split = true;
        Ahi = g_ha_hi; Alo = g_ha_lo;
        int n0g = n * 128;
        if (n0g < 2048)      { Bh = g_wq_hi;  Bl = g_wq_lo;  n0 = n0g;        map = 3; dest = 2; Nl = 2048; }
        else if (n0g < 2560) { Bh = g_wka_hi; Bl = g_wka_lo; n0 = n0g - 2048; map = 2; dest = 0; Nl = 512; }
        else                 { Bh = g_wva_hi; Bl = g_wva_lo; n0 = n0g - 2560; map = 2; dest = 1; Nl = 512; }
    }

    auto load_stage = [&](int stage, int kof) {
        uint32_t stb = sbase + stage * 49152;
#pragma unroll
        for (int it = 0; it < 2; ++it) {
            int idx = tid + it * 256;
            int r = idx >> 3, ch = idx & 7;
            uint32_t so = swz((uint32_t)(r * 128 + ch * 16));
            CP_ASYNC16(stb + so,        Ahi + (size_t)(m0 + r) * K + kof + ch * 8);
            CP_ASYNC16(stb + 8192 + so, Alo + (size_t)(m0 + r) * K + kof + ch * 8);
        }
#pragma unroll
        for (int it = 0; it < 4; ++it) {
            int idx = tid + it * 256;
            int r = idx >> 3, ch = idx & 7;
            uint32_t so = swz((uint32_t)(r * 128 + ch * 16));
            CP_ASYNC16(stb + 16384 + so, Bh + (size_t)(n0 + r) * K + kof + ch * 8);
            CP_ASYNC16(stb + 32768 + so, Bl + (size_t)(n0 + r) * K + kof + ch * 8);
        }
    };

    float acc[2][4][4];
#pragma unroll
    for (int i = 0; i < 2; ++i)
#pragma unroll
        for (int j = 0; j < 4; ++j)
#pragma unroll
            for (int k = 0; k < 4; ++k) acc[i][j][k] = 0.f;

    load_stage(0, kstart);
    CP_COMMIT();

    const uint32_t aRow = wm * 32 + (lane & 15);
    const uint32_t aKof = (lane >> 4) * 8;
    const uint32_t bRow = wn * 32 + ((lane >> 4) * 8) + (lane & 7);
    const uint32_t bKof = ((lane >> 3) & 1) * 8;

    for (int c = 0; c < nch; ++c) {
        if (c + 1 < nch) { load_stage((c + 1) & 1, kstart + (c + 1) * 64); CP_COMMIT(); CP_WAIT(1); }
        else             { CP_WAIT(0); }
        __syncthreads();

        uint32_t st = sbase + (c & 1) * 49152;
        uint32_t tAhi = st, tAlo = st + 8192, tBhi = st + 16384, tBlo = st + 32768;

#pragma unroll
        for (int ks = 0; ks < 4; ++ks) {
            uint32_t ahi[2][4], alo[2][4];
#pragma unroll
            for (int mt = 0; mt < 2; ++mt) {
                uint32_t off = swz((aRow + mt * 16) * 128 + (ks * 16 + aKof) * 2);
                ldsm_x4(ahi[mt], tAhi + off);
                ldsm_x4(alo[mt], tAlo + off);
            }
            uint32_t bhi[2][4], blo[2][4];
#pragma unroll
            for (int g = 0; g < 2; ++g) {
                uint32_t off = swz((bRow + g * 16) * 128 + (ks * 16 + bKof) * 2);
                ldsm_x4(bhi[g], tBhi + off);
                ldsm_x4(blo[g], tBlo + off);
            }
#pragma unroll
            for (int mt = 0; mt < 2; ++mt)
#pragma unroll
                for (int nt = 0; nt < 4; ++nt) {
                    const uint32_t* bh4 = &bhi[nt >> 1][(nt & 1) * 2];
                    const uint32_t* bl4 = &blo[nt >> 1][(nt & 1) * 2];
                    mma_bf16(acc[mt][nt], ahi[mt], bh4);
                    mma_bf16(acc[mt][nt], ahi[mt], bl4);
                    mma_bf16(acc[mt][nt], alo[mt], bh4);
                }
        }
        __syncthreads();
    }

    float* C = (dest == 0) ? g_K : (dest == 1) ? g_V : g_q;
#pragma unroll
    for (int mt = 0; mt < 2; ++mt)
#pragma unroll
        for (int nt = 0; nt < 4; ++nt)
#pragma unroll
            for (int e = 0; e < 4; ++e) {
                int r = m0 + wm * 32 + mt * 16 + (lane >> 2) + (e >> 1) * 8;
                int cc = n0 + wn * 32 + nt * 8 + 2 * (lane & 3) + (e & 1);
                int idx = out_index(map, r, cc, Nl);
                if (split) atomicAdd(&C[idx], acc[mt][nt][e]);
                else       C[idx] = acc[mt][nt][e];
            }
}

// ---------------- Wo GEMM (validated round 12) ----------------
__global__ void __launch_bounds__(256, 2) tc_wo(float* __restrict__ Cext)
{
    extern __shared__ char smem[];
    uint32_t sbase = smem_to_u32(smem);

    const int tid = threadIdx.x, lane = tid & 31, wid = tid >> 5;
    const int wm = wid & 1, wn = wid >> 1;
    const int m0 = blockIdx.y * 64;
    const int n0 = blockIdx.x * 128;
    const int kstart = blockIdx.z * 512;
    const int K = 2048, nch = 8;

    auto load_stage = [&](int stage, int kof) {
        uint32_t stb = sbase + stage * 49152;
#pragma unroll
        for (int it = 0; it < 2; ++it) {
            int idx = tid + it * 256;
            int r = idx >> 3, ch = idx & 7;
            uint32_t so = swz((uint32_t)(r * 128 + ch * 16));
            CP_ASYNC16(stb + so,        g_at_hi + (size_t)(m0 + r) * K + kof + ch * 8);
            CP_ASYNC16(stb + 8192 + so, g_at_lo + (size_t)(m0 + r) * K + kof + ch * 8);
        }
#pragma unroll
        for (int it = 0; it < 4; ++it) {
            int idx = tid + it * 256;
            int r = idx >> 3, ch = idx & 7;
            uint32_t so = swz((uint32_t)(r * 128 + ch * 16));
            CP_ASYNC16(stb + 16384 + so, g_wo_hi + (size_t)(n0 + r) * K + kof + ch * 8);
            CP_ASYNC16(stb + 32768 + so, g_wo_lo + (size_t)(n0 + r) * K + kof + ch * 8);
        }
    };

    float acc[2][4][4];
#pragma unroll
    for (int i = 0; i < 2; ++i)
#pragma unroll
        for (int j = 0; j < 4; ++j)
#pragma unroll
            for (int k = 0; k < 4; ++k) acc[i][j][k] = 0.f;

    load_stage(0, kstart);
    CP_COMMIT();

    const uint32_t aRow = wm * 32 + (lane & 15);
    const uint32_t aKof = (lane >> 4) * 8;
    const uint32_t bRow = wn * 32 + ((lane >> 4) * 8) + (lane & 7);
    const uint32_t bKof = ((lane >> 3) & 1) * 8;

    for (int c = 0; c < nch; ++c) {
        if (c + 1 < nch) { load_stage((c + 1) & 1, kstart + (c + 1) * 64); CP_COMMIT(); CP_WAIT(1); }
        else             { CP_WAIT(0); }
        __syncthreads();

        uint32_t st = sbase + (c & 1) * 49152;
        uint32_t tAhi = st, tAlo = st + 8192, tBhi = st + 16384, tBlo = st + 32768;

#pragma unroll
        for (int ks = 0; ks < 4; ++ks) {
            uint32_t ahi[2][4], alo[2][4];
#pragma unroll
            for (int mt = 0; mt < 2; ++mt) {
                uint32_t off = swz((aRow + mt * 16) * 128 + (ks * 16 + aKof) * 2);
                ldsm_x4(ahi[mt], tAhi + off);
                ldsm_x4(alo[mt], tAlo + off);
            }
            uint32_t bhi[2][4], blo[2][4];
#pragma unroll
            for (int g = 0; g < 2; ++g) {
                uint32_t off = swz((bRow + g * 16) * 128 + (ks * 16 + bKof) * 2);
                ldsm_x4(bhi[g], tBhi + off);
                ldsm_x4(blo[g], tBlo + off);
            }
#pragma unroll
            for (int mt = 0; mt < 2; ++mt)
#pragma unroll
                for (int nt = 0; nt < 4; ++nt) {
                    const uint32_t* bh4 = &bhi[nt >> 1][(nt & 1) * 2];
                    const uint32_t* bl4 = &blo[nt >> 1][(nt & 1) * 2];
                    mma_bf16(acc[mt][nt], ahi[mt], bh4);
                    mma_bf16(acc[mt][nt], ahi[mt], bl4);
                    mma_bf16(acc[mt][nt], alo[mt], bh4);
                }
        }
        __syncthreads();
    }

#pragma unroll
    for (int mt = 0; mt < 2; ++mt)
#pragma unroll
        for (int nt = 0; nt < 4; ++nt)
#pragma unroll
            for (int e = 0; e < 4; ++e) {
                int r = m0 + wm * 32 + mt * 16 + (lane >> 2) + (e >> 1) * 8;
                int cc = n0 + wn * 32 + nt * 8 + 2 * (lane & 3) + (e & 1);
                atomicAdd(&Cext[(size_t)r * 2048 + cc], acc[mt][nt][e]);
            }
}

// ---------------- HMMA attention scores: Q resident, 3 K-chunks per block -------
// grid (7, 64). smem: Q 32KB resident + K double-buffered 2x32KB = 96KB.
// Q layout: qh c0 @0, qh c1 @8K, ql c0 @16K, ql c1 @24K.
// K stage s (@32K + s*32K): Kh c0, Kh c1, Kl c0, Kl c1 (8KB each).
__global__ void __launch_bounds__(256, 2) score_hmma(const float* __restrict__ mask)
{
    extern __shared__ char smem[];
    uint32_t sbase = smem_to_u32(smem);

    const int tid = threadIdx.x, lane = tid & 31, wid = tid >> 5;
    const int wm = wid & 1, wn = wid >> 1;
    int bh = blockIdx.y;
    int b = bh >> 4, h = bh & 15, kv = h >> 2;
    int sc0 = blockIdx.x * 3;

    size_t koff0 = (size_t)(b * NKV + kv) * STOT;

    auto load_K = [&](int stage, int s0) {
#pragma unroll
        for (int it = 0; it < 2; ++it) {
            int idx = tid + it * 256;
            int r = idx >> 3, ch = idx & 7;
            uint32_t so = swz((uint32_t)(r * 128 + ch * 16));
            uint32_t stb = sbase + 32768 + stage * 32768;
            size_t koff = (koff0 + s0 + r) * HDIM;
#pragma unroll
            for (int c = 0; c < 2; ++c) {
                CP_ASYNC16(stb + c * 8192 + so,           g_Kh + koff + c * 64 + ch * 8);
                CP_ASYNC16(stb + 16384 + c * 8192 + so,   g_Kl + koff + c * 64 + ch * 8);
            }
        }
    };

    // load Q (resident) + first K stage, one commit group
#pragma unroll
    for (int it = 0; it < 2; ++it) {
        int idx = tid + it * 256;
        int r = idx >> 3, ch = idx & 7;
        uint32_t so = swz((uint32_t)(r * 128 + ch * 16));
        size_t qoff = (size_t)(bh * 64 + r) * HDIM;
#pragma unroll
        for (int c = 0; c < 2; ++c) {
            CP_ASYNC16(sbase + c * 8192 + so,          g_qh + qoff + c * 64 + ch * 8);
            CP_ASYNC16(sbase + 16384 + c * 8192 + so,  g_ql + qoff + c * 64 + ch * 8);
        }
    }
    load_K(0, sc0 * 64);
    CP_COMMIT();

    const uint32_t aRow = wm * 32 + (lane & 15);
    const uint32_t aKof = (lane >> 4) * 8;
    const uint32_t bRow = wn * 16 + ((lane >> 4) * 8) + (lane & 7);
    const uint32_t bKof = ((lane >> 3) & 1) * 8;
    const float scale = 0.08838834764831845f;

    for (int sc = 0; sc < 3; ++sc) {
        int s0 = (sc0 + sc) * 64;
        if (sc + 1 < 3) { load_K((sc + 1) & 1, s0 + 64); CP_COMMIT(); CP_WAIT(1); }
        else            { CP_WAIT(0); }
        __syncthreads();

        float acc[2][2][4];
#pragma unroll
        for (int i = 0; i < 2; ++i)
#pragma unroll
            for (int j = 0; j < 2; ++j)
#pragma unroll
                for (int k = 0; k < 4; ++k) acc[i][j][k] = 0.f;

        uint32_t kst = sbase + 32768 + (sc & 1) * 32768;

#pragma unroll
        for (int c = 0; c < 2; ++c) {
            uint32_t tqh = sbase + c * 8192, tql = sbase + 16384 + c * 8192;
            uint32_t tkh = kst + c * 8192,  tkl = kst + 16384 + c * 8192;
#pragma unroll
            for (int ks = 0; ks < 4; ++ks) {
                uint32_t ahi[2][4], alo[2][4];
#pragma unroll
                for (int mt = 0; mt < 2; ++mt) {
                    uint32_t off = swz((aRow + mt * 16) * 128 + (ks * 16 + aKof) * 2);
                    ldsm_x4(ahi[mt], tqh + off);
                    ldsm_x4(alo[mt], tql + off);
                }
                uint32_t bh4[4], bl4[4];
                {
                    uint32_t off = swz(bRow * 128 + (ks * 16 + bKof) * 2);
                    ldsm_x4(bh4, tkh + off);
                    ldsm_x4(bl4, tkl + off);
                }
#pragma unroll
                for (int mt = 0; mt < 2; ++mt)
#pragma unroll
                    for (int nt = 0; nt < 2; ++nt) {
                        mma_bf16(acc[mt][nt], ahi[mt], &bh4[nt * 2]);
                        mma_bf16(acc[mt][nt], ahi[mt], &bl4[nt * 2]);
                        mma_bf16(acc[mt][nt], alo[mt], &bh4[nt * 2]);
                    }
            }
        }

#pragma unroll
        for (int mt = 0; mt < 2; ++mt)
#pragma unroll
            for (int nt = 0; nt < 2; ++nt)
#pragma unroll
                for (int e = 0; e < 4; ++e) {
                    int q = wm * 32 + mt * 16 + (lane >> 2) + (e >> 1) * 8;
                    int s = s0 + wn * 16 + nt * 8 + 2 * (lane & 3) + (e & 1);
                    float v = acc[mt][nt][e] * scale;
                    v = tanhf(v * 0.02f) * 50.0f
                      + mask[(size_t)b * (1088 * 1344) + (size_t)(1024 + q) * 1344 + s];
                    g_scores[(size_t)(bh * 64 + q) * STOT + s] = v;
                }
        __syncthreads();
    }
}

// ---------------- HMMA P @ V (validated) ----------------
__global__ void __launch_bounds__(256) pv_hmma()
{
    extern __shared__ char smem[];
    uint32_t sbase = smem_to_u32(smem);

    const int tid = threadIdx.x, lane = tid & 31, wid = tid >> 5;
    const int wm = wid & 1, wn = wid >> 1;
    int bh = blockIdx.x;
    int b = bh >> 4, h = bh & 15, kv = h >> 2;
    int kc0 = blockIdx.y * 192;

    size_t prow0 = (size_t)bh * 64;
    size_t vrow0 = (size_t)(b * NKV + kv) * HDIM;

    auto load_sub = [&](int stage, int kc) {
        uint32_t stb = sbase + stage * 49152;
#pragma unroll
        for (int it = 0; it < 2; ++it) {
            int idx = tid + it * 256;
            int r = idx >> 3, ch = idx & 7;
            uint32_t so = swz((uint32_t)(r * 128 + ch * 16));
            CP_ASYNC16(stb + so,        g_Ph + (prow0 + r) * STOT + kc + ch * 8);
            CP_ASYNC16(stb + 8192 + so, g_Pl + (prow0 + r) * STOT + kc + ch * 8);
        }
#pragma unroll
        for (int it = 0; it < 4; ++it) {
            int idx = tid + it * 256;
            int r = idx >> 3, ch = idx & 7;
            uint32_t so = swz((uint32_t)(r * 128 + ch * 16));
            CP_ASYNC16(stb + 16384 + so, g_Vth + (vrow0 + r) * STOT + kc + ch * 8);
            CP_ASYNC16(stb + 32768 + so, g_Vtl + (vrow0 + r) * STOT + kc + ch * 8);
        }
    };

    float acc[2][4][4];
#pragma unroll
    for (int i = 0; i < 2; ++i)
#pragma unroll
        for (int j = 0; j < 4; ++j)
#pragma unroll
            for (int k = 0; k < 4; ++k) acc[i][j][k] = 0.f;

    load_sub(0, kc0);
    CP_COMMIT();

    const uint32_t aRow = wm * 32 + (lane & 15);
    const uint32_t aKof = (lane >> 4) * 8;
    const uint32_t bRow = wn * 32 + ((lane >> 4) * 8) + (lane & 7);
    const uint32_t bKof = ((lane >> 3) & 1) * 8;

    for (int sub = 0; sub < 3; ++sub) {
        if (sub + 1 < 3) { load_sub((sub + 1) & 1, kc0 + (sub + 1) * 64); CP_COMMIT(); CP_WAIT(1); }
        else             { CP_WAIT(0); }
        __syncthreads();

        uint32_t st = sbase + (sub & 1) * 49152;
        uint32_t tph = st, tpl = st + 8192, tvh = st + 16384, tvl = st + 32768;

#pragma unroll
        for (int ks = 0; ks < 4; ++ks) {
            uint32_t ahi[2][4], alo[2][4];
#pragma unroll
            for (int mt = 0; mt < 2; ++mt) {
                uint32_t off = swz((aRow + mt * 16) * 128 + (ks * 16 + aKof) * 2);
                ldsm_x4(ahi[mt], tph + off);
                ldsm_x4(alo[mt], tpl + off);
            }
            uint32_t bhi[2][4], blo[2][4];
#pragma unroll
            for (int g = 0; g < 2; ++g) {
                uint32_t off = swz((bRow + g * 16) * 128 + (ks * 16 + bKof) * 2);
                ldsm_x4(bhi[g], tvh + off);
                ldsm_x4(blo[g], tvl + off);
            }
#pragma unroll
            for (int mt = 0; mt < 2; ++mt)
#pragma unroll
                for (int nt = 0; nt < 4; ++nt) {
                    const uint32_t* bh4 = &bhi[nt >> 1][(nt & 1) * 2];
                    const uint32_t* bl4 = &blo[nt >> 1][(nt & 1) * 2];
                    mma_bf16(acc[mt][nt], ahi[mt], bh4);
                    mma_bf16(acc[mt][nt], ahi[mt], bl4);
                    mma_bf16(acc[mt][nt], alo[mt], bh4);
                }
        }
        __syncthreads();
    }

#pragma unroll
    for (int mt = 0; mt < 2; ++mt)
#pragma unroll
        for (int nt = 0; nt < 4; ++nt)
#pragma unroll
            for (int e = 0; e < 4; ++e) {
                int q = wm * 32 + mt * 16 + (lane >> 2) + (e >> 1) * 8;
                int d = wn * 32 + nt * 8 + 2 * (lane & 3) + (e & 1);
                atomicAdd(&g_attn[(size_t)(b * SQA + q) * (NH * HDIM) + h * HDIM + d],
                          acc[mt][nt][e]);
            }
}

// ---------------- conversion helpers ----------------
__device__ __forceinline__ void convA_elem(const float4* x, __nv_bfloat162* hi,
                                           __nv_bfloat162* lo, int i)
{
    float4 v = x[i];
    __nv_bfloat16 h0, h1, h2, h3, l0, l1, l2, l3;
    split_bf16(v.x, h0, l0); split_bf16(v.y, h1, l1);
    split_bf16(v.z, h2, l2); split_bf16(v.w, h3, l3);
    hi[i*2+0] = __halves2bfloat162(h0, h1);
    hi[i*2+1] = __halves2bfloat162(h2, h3);
    lo[i*2+0] = __halves2bfloat162(l0, l1);
    lo[i*2+1] = __halves2bfloat162(l2, l3);
}

__device__ __forceinline__ void wt_tile(const float* __restrict__ W,
                                        __nv_bfloat16* bhi, __nv_bfloat16* blo,
                                        int Nd, int k0, int n0, int tx, int ty,
                                        float t[32][33])
{
#pragma unroll
    for (int i = 0; i < 4; ++i)
        t[ty + i*8][tx] = W[(size_t)(k0 + ty + i*8)*Nd + n0 + tx];
    __syncthreads();
#pragma unroll
    for (int i = 0; i < 4; ++i) {
        int n = ty + i*8;
        float v = t[tx][n];
        __nv_bfloat16 h, l; split_bf16(v, h, l);
        size_t o = (size_t)(n0 + n)*2048 + k0 + tx;
        bhi[o] = h; blo[o] = l;
    }
}

// ================= prep1 (validated round 13) =====
#define PREP1_BLOCKS (1024 + 8192 + 512 + 12288)
__global__ void __launch_bounds__(256) prep1_kernel(
    float* out, const float* __restrict__ kc, const float* __restrict__ vc,
    const float* __restrict__ h_vlm, const float* __restrict__ h_act,
    const float* Wkv, const float* Wvv, const float* Wq,
    const float* Wka, const float* Wva, const float* Wo)
{
    __shared__ float t[32][33];
    int bid = blockIdx.x;

    if (bid < 1024) {
        int tid = bid * 256 + threadIdx.x;
        const int stride = 1024 * 256;
        const int nq = BB*NH*SQA*HDIM;
        const int na = BB*SQA*NH*HDIM;
        const int no = BB*SQA*DMODEL;
        const int nact = BB*NKV*SQA*HDIM;
        const int ncache = BB*NKV*SCACHE*HDIM;
        for (int i = tid; i < nq; i += stride) g_q[i] = 0.f;
        for (int i = tid; i < na; i += stride) g_attn[i] = 0.f;
        for (int i = tid; i < no; i += stride) out[i] = 0.f;
        for (int i = tid; i < nact; i += stride) {
            int d  = i & 127;
            int s  = (i >> 7) & 63;
            int bk = i >> 13;
            int idx = (bk*STOT + (SCACHE + SQV) + s)*HDIM + d;
            g_K[idx] = 0.f;
            g_V[idx] = 0.f;
        }
        for (int i = tid; i < ncache; i += stride) {
            int d  = i & 127;
            int s  = (i >> 7) & 255;
            int bk = i >> 15;
            int dst = (bk*STOT + s)*HDIM + d;
            __nv_bfloat16 h, l; split_bf16(kc[i], h, l);
            g_Kh[dst] = h; g_Kl[dst] = l;     // cache keys NOT roped
            g_V[dst] = vc[i];
        }
    } else if (bid < 9216) {
        int i = (bid - 1024) * 256 + threadIdx.x;
        convA_elem((const float4*)h_vlm, (__nv_bfloat162*)g_hv_hi, (__nv_bfloat162*)g_hv_lo, i);
    } else if (bid < 9728) {
        int i = (bid - 9216) * 256 + threadIdx.x;
        convA_elem((const float4*)h_act, (__nv_bfloat162*)g_ha_hi, (__nv_bfloat162*)g_ha_lo, i);
    } else {
        int bx = bid - 9728;
        int tx = threadIdx.x & 31, ty = threadIdx.x >> 5;
        if (bx < 1024)       { int l = bx;        wt_tile(Wkv, g_wkv_hi, g_wkv_lo,  512, (l>>4)*32, (l&15)*32, tx, ty, t); }
        else if (bx < 2048)  { int l = bx - 1024; wt_tile(Wvv, g_wvv_hi, g_wvv_lo,  512, (l>>4)*32, (l&15)*32, tx, ty, t); }
        else if (bx < 6144)  { int l = bx - 2048; wt_tile(Wq,  g_wq_hi,  g_wq_lo,  2048, (l>>6)*32, (l&63)*32, tx, ty, t); }
        else if (bx < 7168)  { int l = bx - 6144; wt_tile(Wka, g_wka_hi, g_wka_lo,  512, (l>>4)*32, (l&15)*32, tx, ty, t); }
        else if (bx < 8192)  { int l = bx - 7168; wt_tile(Wva, g_wva_hi, g_wva_lo,  512, (l>>4)*32, (l&15)*32, tx, ty, t); }
        else                 { int l = bx - 8192; wt_tile(Wo,  g_wo_hi,  g_wo_lo,  2048, (l>>6)*32, (l&63)*32, tx, ty, t); }
    }
}

// ================= prep2 (validated round 13) =====
#define ROPE_T0 (BB*NKV*SQV*64)
#define ROPE_T1 (BB*NKV*SQA*64)
#define ROPE_T2 (BB*NH*SQA*64)
#define PREP2_BLOCKS (5376 + 2688)
__global__ void __launch_bounds__(256) prep2_kernel(
    const int* __restrict__ pos_vlm, const int* __restrict__ pos_act)
{
    __shared__ float t[32][33];
    int bid = blockIdx.x;

    if (bid < 5376) {
        int idx = bid * 256 + threadIdx.x;
        int which, nh, seqlen, s_off;
        const int* pos;
        if (idx < ROPE_T0) { which = 0; pos = pos_vlm; nh = NKV; seqlen = SQV; s_off = SCACHE; }
        else if (idx < ROPE_T0 + ROPE_T1) {
            idx -= ROPE_T0; which = 0; pos = pos_act; nh = NKV; seqlen = SQA; s_off = SCACHE + SQV;
        }
        else {
            idx -= ROPE_T0 + ROPE_T1; which = 1; pos = pos_act; nh = NH; seqlen = SQA; s_off = 0;
        }

        int i = idx & 63;
        int rest = idx >> 6;
        int s = rest % seqlen; rest /= seqlen;
        int hh = rest % nh;
        int b  = rest / nh;

        const float* X = (which == 0) ? g_K : g_q;
        __nv_bfloat16* Xh = (which == 0) ? g_Kh : g_qh;
        __nv_bfloat16* Xl = (which == 0) ? g_Kl : g_ql;
        int stot = (which == 0) ? STOT : SQA;

        int p = pos[b*seqlen + s];
        float inv = exp2f(-0.20762050593046868f * (float)i);
        float ang = (float)p * inv;
        double ad  = (double)ang;
        double red = ad - rint(ad * 0.15915494309189535) * 6.283185307179586;
        float c  = cosf((float)red);
        float sn = sinf((float)red);

        size_t base = ((size_t)((b*nh + hh)*stot + s_off + s)) * HDIM;
        float x1 = X[base + i], x2 = X[base + 64 + i];
        float r1 = x1*c - x2*sn;
        float r2 = x2*c + x1*sn;
        __nv_bfloat16 h, l;
        split_bf16(r1, h, l); Xh[base + i] = h;       Xl[base + i] = l;
        split_bf16(r2, h, l); Xh[base + 64 + i] = h;  Xl[base + 64 + i] = l;
    } else {
        int l = bid - 5376;
        int d0 = (l & 3) * 32;
        int s0 = ((l >> 2) % 42) * 32;
        int z  = l / 168;
        int tx = threadIdx.x & 31, ty = threadIdx.x >> 5;
        const float* V = g_V + (size_t)z*STOT*HDIM;
#pragma unroll
        for (int i = 0; i < 4; ++i)
            t[ty + i*8][tx] = V[(size_t)(s0 + ty + i*8)*HDIM + d0 + tx];
        __syncthreads();
#pragma unroll
        for (int i = 0; i < 4; ++i) {
            int d = ty + i*8;
            float v = t[tx][d];
            __nv_bfloat16 h, l2; split_bf16(v, h, l2);
            size_t o = (size_t)z*HDIM*STOT + (size_t)(d0 + d)*STOT + s0 + tx;
            g_Vth[o] = h; g_Vtl[o] = l2;
        }
    }
}

// ---------------- attn -> bf16 hi/lo ----------------
__global__ void convAT_kernel()
{
    int i = blockIdx.x*blockDim.x + threadIdx.x;
    if (i >= 256*2048/4) return;
    convA_elem((const float4*)g_attn, (__nv_bfloat162*)g_at_hi, (__nv_bfloat162*)g_at_lo, i);
}

// ---------------- row softmax -> P bf16 hi/lo ----------------
__global__ void softmax_kernel()
{
    int row  = blockIdx.x*4 + (threadIdx.x >> 5);
    int lane = threadIdx.x & 31;
    const float* p = g_scores + (size_t)row * STOT;

    float vals[42];
    float m = -1e30f;
#pragma unroll
    for (int i = 0; i < 42; i++) { vals[i] = p[i*32 + lane]; m = fmaxf(m, vals[i]); }
#pragma unroll
    for (int off = 16; off > 0; off >>= 1) m = fmaxf(m, __shfl_xor_sync(0xffffffffu, m, off));
    float sum = 0.f;
#pragma unroll
    for (int i = 0; i < 42; i++) { vals[i] = __expf(vals[i] - m); sum += vals[i]; }
#pragma unroll
    for (int off = 16; off > 0; off >>= 1) sum += __shfl_xor_sync(0xffffffffu, sum, off);
    float invs = 1.0f / sum;
    __nv_bfloat16* ph = g_Ph + (size_t)row * STOT;
    __nv_bfloat16* pl = g_Pl + (size_t)row * STOT;
#pragma unroll
    for (int i = 0; i < 42; i++) {
        float v = vals[i] * invs;
        __nv_bfloat16 h, l; split_bf16(v, h, l);
        ph[i*32 + lane] = h;
        pl[i*32 + lane] = l;
    }
}

// ---------------- launch ----------------
extern "C" void kernel_launch(void* const* d_in, const int* in_sizes, int n_in,
                              void* d_out, int out_size)
{
    (void)in_sizes; (void)n_in; (void)out_size;
    const float* mask    = (const float*)d_in[0];
    const int*   pos_vlm = (const int*)  d_in[1];
    const int*   pos_act = (const int*)  d_in[2];
    const float* h_vlm   = (const float*)d_in[3];
    const float* h_act   = (const float*)d_in[4];
    const float* k_cache = (const float*)d_in[5];
    const float* v_cache = (const float*)d_in[6];
    // d_in[7] = Wq_vlm: unused (q_vlm rows are discarded by reference)
    const float* Wk_vlm  = (const float*)d_in[8];
    const float* Wv_vlm  = (const float*)d_in[9];
    const float* Wq_act  = (const float*)d_in[10];
    const float* Wk_act  = (const float*)d_in[11];
    const float* Wv_act  = (const float*)d_in[12];
    const float* Wo_act  = (const float*)d_in[13];
    float* out = (float*)d_out;

    cudaFuncSetAttribute(tc_proj,    cudaFuncAttributeMaxDynamicSharedMemorySize, TCG_SMEM_BYTES);
    cudaFuncSetAttribute(tc_wo,      cudaFuncAttributeMaxDynamicSharedMemorySize, TCG_SMEM_BYTES);
    cudaFuncSetAttribute(score_hmma, cudaFuncAttributeMaxDynamicSharedMemorySize, 98304);
    cudaFuncSetAttribute(pv_hmma,    cudaFuncAttributeMaxDynamicSharedMemorySize, 98304);

    // 1. prep1: zero/copy + activation conversions + weight transposes
    prep1_kernel<<<PREP1_BLOCKS, 256>>>(out, k_cache, v_cache, h_vlm, h_act,
                                        Wk_vlm, Wv_vlm, Wq_act, Wk_act, Wv_act, Wo_act);

    // 2. ALL projections (vlm KV + act QKV) in ONE launch
    tc_proj<<<896, 256, TCG_SMEM_BYTES>>>();

    // 3. prep2: RoPE+bf16 conversion + V transpose
    prep2_kernel<<<PREP2_BLOCKS, 256>>>(pos_vlm, pos_act);

    // 4-6. attention on HMMA (score: Q-resident, 3 chunks/block)
    score_hmma<<<dim3(7, 64), 256, 98304>>>(mask);
    softmax_kernel<<<1024, 128>>>();
    pv_hmma<<<dim3(64, 7), 256, 98304>>>();

    // 7. attn -> bf16 hi/lo
    convAT_kernel<<<(256*2048/4 + 255)/256, 256>>>();

    // 8. output projection, split-K 4
    tc_wo<<<dim3(16, 4, 4), 256, TCG_SMEM_BYTES>>>(out);
}

// round 15
// speedup vs baseline: 1.0080x; 1.0080x over previous
#include <cuda_runtime.h>
#include <cuda_bf16.h>
#include <math.h>
#include <stdint.h>

// ---------------- problem constants ----------------
#define BB      4
#define NH      16
#define NKV     4
#define HDIM    128
#define DMODEL  2048
#define SQV     1024
#define SQA     64
#define SCACHE  256
#define STOT    1344
#define NQROWS  (BB*NH*SQA)

// ---------------- fp32 scratch ----------------
__device__ float g_K[BB*NKV*STOT*HDIM];
__device__ float g_V[BB*NKV*STOT*HDIM];
__device__ float g_q[BB*NH*SQA*HDIM];
__device__ float g_scores[NQROWS*STOT];
__device__ float g_attn[BB*SQA*NH*HDIM];

// ---------------- bf16 split operands (hi + lo) ----------------
__device__ __nv_bfloat16 g_hv_hi[4096*2048], g_hv_lo[4096*2048];
__device__ __nv_bfloat16 g_ha_hi[256*2048],  g_ha_lo[256*2048];
__device__ __nv_bfloat16 g_at_hi[256*2048],  g_at_lo[256*2048];
__device__ __nv_bfloat16 g_wkv_hi[512*2048], g_wkv_lo[512*2048];
__device__ __nv_bfloat16 g_wvv_hi[512*2048], g_wvv_lo[512*2048];
__device__ __nv_bfloat16 g_wq_hi[2048*2048], g_wq_lo[2048*2048];
__device__ __nv_bfloat16 g_wka_hi[512*2048], g_wka_lo[512*2048];
__device__ __nv_bfloat16 g_wva_hi[512*2048], g_wva_lo[512*2048];
__device__ __nv_bfloat16 g_wo_hi[2048*2048], g_wo_lo[2048*2048];

// attention bf16 operands
__device__ __nv_bfloat16 g_qh[BB*NH*SQA*HDIM],  g_ql[BB*NH*SQA*HDIM];
__device__ __nv_bfloat16 g_Kh[BB*NKV*STOT*HDIM], g_Kl[BB*NKV*STOT*HDIM];
__device__ __nv_bfloat16 g_Vth[BB*NKV*HDIM*STOT], g_Vtl[BB*NKV*HDIM*STOT];
__device__ __nv_bfloat16 g_Ph[NQROWS*STOT], g_Pl[NQROWS*STOT];

// ================= PTX helpers =================
__device__ __forceinline__ uint32_t smem_to_u32(const void* p) {
    uint32_t a;
    asm("{ .reg .u64 t; cvta.to.shared.u64 t, %1; cvt.u32.u64 %0, t; }" : "=r"(a) : "l"(p));
    return a;
}
#define CP_ASYNC16(sm, gm) \
    asm volatile("cp.async.cg.shared.global [%0], [%1], 16;" :: "r"(sm), "l"(gm))
#define CP_COMMIT() asm volatile("cp.async.commit_group;" ::: "memory")
#define CP_WAIT(n)  asm volatile("cp.async.wait_group %0;" :: "n"(n) : "memory")

__device__ __forceinline__ void ldsm_x4(uint32_t* r, uint32_t addr) {
    asm volatile("ldmatrix.sync.aligned.m8n8.x4.shared.b16 {%0,%1,%2,%3}, [%4];"
        : "=r"(r[0]), "=r"(r[1]), "=r"(r[2]), "=r"(r[3]) : "r"(addr));
}
__device__ __forceinline__ void mma_bf16(float* d, const uint32_t* a, const uint32_t* b) {
    asm volatile("mma.sync.aligned.m16n8k16.row.col.f32.bf16.bf16.f32 "
        "{%0,%1,%2,%3}, {%4,%5,%6,%7}, {%8,%9}, {%0,%1,%2,%3};"
        : "+f"(d[0]), "+f"(d[1]), "+f"(d[2]), "+f"(d[3])
        : "r"(a[0]), "r"(a[1]), "r"(a[2]), "r"(a[3]), "r"(b[0]), "r"(b[1]));
}
__device__ __forceinline__ uint32_t swz(uint32_t off) { return off ^ ((off >> 3) & 0x70); }

__device__ __forceinline__ void split_bf16(float v, __nv_bfloat16& h, __nv_bfloat16& l) {
    h = __float2bfloat16(v);
    l = __float2bfloat16(v - __bfloat162float(h));
}

// fast exact-limit tanh: 1 - 2/(e^{2u}+1). expf overflow/underflow give exact +-1.
__device__ __forceinline__ float fast_tanh(float u) {
    return 1.0f - __fdividef(2.0f, __expf(2.0f * u) + 1.0f);
}

// ---------------- output index mapping ----------------
__device__ __forceinline__ int out_index(int map, int r, int c, int N) {
    switch (map) {
        case 1: { int b=r>>10, s=r&1023, kv=c>>7, d=c&127;
                  return (((b*NKV+kv)*STOT) + SCACHE + s)*HDIM + d; }
        case 2: { int b=r>>6, s=r&63, kv=c>>7, d=c&127;
                  return (((b*NKV+kv)*STOT) + (SCACHE+SQV) + s)*HDIM + d; }
        case 3: { int b=r>>6, s=r&63, h=c>>7, d=c&127;
                  return (((b*NH+h)*SQA) + s)*HDIM + d; }
        default: return r*N + c;
    }
}

// ---------------- merged projection GEMM (validated round 12) ----------------
#define TCG_SMEM_BYTES (98304)
__global__ void __launch_bounds__(256, 2) tc_proj()
{
    extern __shared__ char smem[];
    uint32_t sbase = smem_to_u32(smem);

    const int tid = threadIdx.x, lane = tid & 31, wid = tid >> 5;
    const int wm = wid & 1, wn = wid >> 1;

    int bid = blockIdx.x;
    const __nv_bfloat16 *Ahi, *Alo, *Bh, *Bl;
    int m0, n0, kstart, nch, map, dest, Nl;
    bool split;
    const int K = 2048;

    if (bid < 512) {
        int n = bid & 7, m = bid >> 3;
        m0 = m * 64; kstart = 0; nch = 32; split = false;
        Ahi = g_hv_hi; Alo = g_hv_lo;
        int n0g = n * 128;
        if (n0g < 512) { Bh = g_wkv_hi; Bl = g_wkv_lo; n0 = n0g;       map = 1; dest = 0; Nl = 512; }
        else           { Bh = g_wvv_hi; Bl = g_wvv_lo; n0 = n0g - 512; map = 1; dest = 1; Nl = 512; }
    } else {
        int l = bid - 512;
        int n = l % 24; l /= 24;
        int m = l & 3;  int z = l >> 2;
        m0 = m * 64; kstart = z * 512; nch = 8; split = true;
        Ahi = g_ha_hi; Alo = g_ha_lo;
        int n0g = n * 128;
        if (n0g < 2048)      { Bh = g_wq_hi;  Bl = g_wq_lo;  n0 = n0g;        map = 3; dest = 2; Nl = 2048; }
        else if (n0g < 2560) { Bh = g_wka_hi; Bl = g_wka_lo; n0 = n0g - 2048; map = 2; dest = 0; Nl = 512; }
        else                 { Bh = g_wva_hi; Bl = g_wva_lo; n0 = n0g - 2560; map = 2; dest = 1; Nl = 512; }
    }

    auto load_stage = [&](int stage, int kof) {
        uint32_t stb = sbase + stage * 49152;
#pragma unroll
        for (int it = 0; it < 2; ++it) {
            int idx = tid + it * 256;
            int r = idx >> 3, ch = idx & 7;
            uint32_t so = swz((uint32_t)(r * 128 + ch * 16));
            CP_ASYNC16(stb + so,        Ahi + (size_t)(m0 + r) * K + kof + ch * 8);
            CP_ASYNC16(stb + 8192 + so, Alo + (size_t)(m0 + r) * K + kof + ch * 8);
        }
#pragma unroll
        for (int it = 0; it < 4; ++it) {
            int idx = tid + it * 256;
            int r = idx >> 3, ch = idx & 7;
            uint32_t so = swz((uint32_t)(r * 128 + ch * 16));
            CP_ASYNC16(stb + 16384 + so, Bh + (size_t)(n0 + r) * K + kof + ch * 8);
            CP_ASYNC16(stb + 32768 + so, Bl + (size_t)(n0 + r) * K + kof + ch * 8);
        }
    };

    float acc[2][4][4];
#pragma unroll
    for (int i = 0; i < 2; ++i)
#pragma unroll
        for (int j = 0; j < 4; ++j)
#pragma unroll
            for (int k = 0; k < 4; ++k) acc[i][j][k] = 0.f;

    load_stage(0, kstart);
    CP_COMMIT();

    const uint32_t aRow = wm * 32 + (lane & 15);
    const uint32_t aKof = (lane >> 4) * 8;
    const uint32_t bRow = wn * 32 + ((lane >> 4) * 8) + (lane & 7);
    const uint32_t bKof = ((lane >> 3) & 1) * 8;

    for (int c = 0; c < nch; ++c) {
        if (c + 1 < nch) { load_stage((c + 1) & 1, kstart + (c + 1) * 64); CP_COMMIT(); CP_WAIT(1); }
        else             { CP_WAIT(0); }
        __syncthreads();

        uint32_t st = sbase + (c & 1) * 49152;
        uint32_t tAhi = st, tAlo = st + 8192, tBhi = st + 16384, tBlo = st + 32768;

#pragma unroll
        for (int ks = 0; ks < 4; ++ks) {
            uint32_t ahi[2][4], alo[2][4];
#pragma unroll
            for (int mt = 0; mt < 2; ++mt) {
                uint32_t off = swz((aRow + mt * 16) * 128 + (ks * 16 + aKof) * 2);
                ldsm_x4(ahi[mt], tAhi + off);
                ldsm_x4(alo[mt], tAlo + off);
            }
            uint32_t bhi[2][4], blo[2][4];
#pragma unroll
            for (int g = 0; g < 2; ++g) {
                uint32_t off = swz((bRow + g * 16) * 128 + (ks * 16 + bKof) * 2);
                ldsm_x4(bhi[g], tBhi + off);
                ldsm_x4(blo[g], tBlo + off);
            }
#pragma unroll
            for (int mt = 0; mt < 2; ++mt)
#pragma unroll
                for (int nt = 0; nt < 4; ++nt) {
                    const uint32_t* bh4 = &bhi[nt >> 1][(nt & 1) * 2];
                    const uint32_t* bl4 = &blo[nt >> 1][(nt & 1) * 2];
                    mma_bf16(acc[mt][nt], ahi[mt], bh4);
                    mma_bf16(acc[mt][nt], ahi[mt], bl4);
                    mma_bf16(acc[mt][nt], alo[mt], bh4);
                }
        }
        __syncthreads();
    }

    float* C = (dest == 0) ? g_K : (dest == 1) ? g_V : g_q;
#pragma unroll
    for (int mt = 0; mt < 2; ++mt)
#pragma unroll
        for (int nt = 0; nt < 4; ++nt)
#pragma unroll
            for (int e = 0; e < 4; ++e) {
                int r = m0 + wm * 32 + mt * 16 + (lane >> 2) + (e >> 1) * 8;
                int cc = n0 + wn * 32 + nt * 8 + 2 * (lane & 3) + (e & 1);
                int idx = out_index(map, r, cc, Nl);
                if (split) atomicAdd(&C[idx], acc[mt][nt][e]);
                else       C[idx] = acc[mt][nt][e];
            }
}

// ---------------- Wo GEMM (validated round 12) ----------------
__global__ void __launch_bounds__(256, 2) tc_wo(float* __restrict__ Cext)
{
    extern __shared__ char smem[];
    uint32_t sbase = smem_to_u32(smem);

    const int tid = threadIdx.x, lane = tid & 31, wid = tid >> 5;
    const int wm = wid & 1, wn = wid >> 1;
    const int m0 = blockIdx.y * 64;
    const int n0 = blockIdx.x * 128;
    const int kstart = blockIdx.z * 512;
    const int K = 2048, nch = 8;

    auto load_stage = [&](int stage, int kof) {
        uint32_t stb = sbase + stage * 49152;
#pragma unroll
        for (int it = 0; it < 2; ++it) {
            int idx = tid + it * 256;
            int r = idx >> 3, ch = idx & 7;
            uint32_t so = swz((uint32_t)(r * 128 + ch * 16));
            CP_ASYNC16(stb + so,        g_at_hi + (size_t)(m0 + r) * K + kof + ch * 8);
            CP_ASYNC16(stb + 8192 + so, g_at_lo + (size_t)(m0 + r) * K + kof + ch * 8);
        }
#pragma unroll
        for (int it = 0; it < 4; ++it) {
            int idx = tid + it * 256;
            int r = idx >> 3, ch = idx & 7;
            uint32_t so = swz((uint32_t)(r * 128 + ch * 16));
            CP_ASYNC16(stb + 16384 + so, g_wo_hi + (size_t)(n0 + r) * K + kof + ch * 8);
            CP_ASYNC16(stb + 32768 + so, g_wo_lo + (size_t)(n0 + r) * K + kof + ch * 8);
        }
    };

    float acc[2][4][4];
#pragma unroll
    for (int i = 0; i < 2; ++i)
#pragma unroll
        for (int j = 0; j < 4; ++j)
#pragma unroll
            for (int k = 0; k < 4; ++k) acc[i][j][k] = 0.f;

    load_stage(0, kstart);
    CP_COMMIT();

    const uint32_t aRow = wm * 32 + (lane & 15);
    const uint32_t aKof = (lane >> 4) * 8;
    const uint32_t bRow = wn * 32 + ((lane >> 4) * 8) + (lane & 7);
    const uint32_t bKof = ((lane >> 3) & 1) * 8;

    for (int c = 0; c < nch; ++c) {
        if (c + 1 < nch) { load_stage((c + 1) & 1, kstart + (c + 1) * 64); CP_COMMIT(); CP_WAIT(1); }
        else             { CP_WAIT(0); }
        __syncthreads();

        uint32_t st = sbase + (c & 1) * 49152;
        uint32_t tAhi = st, tAlo = st + 8192, tBhi = st + 16384, tBlo = st + 32768;

#pragma unroll
        for (int ks = 0; ks < 4; ++ks) {
            uint32_t ahi[2][4], alo[2][4];
#pragma unroll
            for (int mt = 0; mt < 2; ++mt) {
                uint32_t off = swz((aRow + mt * 16) * 128 + (ks * 16 + aKof) * 2);
                ldsm_x4(ahi[mt], tAhi + off);
                ldsm_x4(alo[mt], tAlo + off);
            }
            uint32_t bhi[2][4], blo[2][4];
#pragma unroll
            for (int g = 0; g < 2; ++g) {
                uint32_t off = swz((bRow + g * 16) * 128 + (ks * 16 + bKof) * 2);
                ldsm_x4(bhi[g], tBhi + off);
                ldsm_x4(blo[g], tBlo + off);
            }
#pragma unroll
            for (int mt = 0; mt < 2; ++mt)
#pragma unroll
                for (int nt = 0; nt < 4; ++nt) {
                    const uint32_t* bh4 = &bhi[nt >> 1][(nt & 1) * 2];
                    const uint32_t* bl4 = &blo[nt >> 1][(nt & 1) * 2];
                    mma_bf16(acc[mt][nt], ahi[mt], bh4);
                    mma_bf16(acc[mt][nt], ahi[mt], bl4);
                    mma_bf16(acc[mt][nt], alo[mt], bh4);
                }
        }
        __syncthreads();
    }

#pragma unroll
    for (int mt = 0; mt < 2; ++mt)
#pragma unroll
        for (int nt = 0; nt < 4; ++nt)
#pragma unroll
            for (int e = 0; e < 4; ++e) {
                int r = m0 + wm * 32 + mt * 16 + (lane >> 2) + (e >> 1) * 8;
                int cc = n0 + wn * 32 + nt * 8 + 2 * (lane & 3) + (e & 1);
                atomicAdd(&Cext[(size_t)r * 2048 + cc], acc[mt][nt][e]);
            }
}

// ---------------- HMMA attention scores: mask prefetch + fast tanh ----------------
// grid (21, 64), block 256. Tile 64q x 64s, K=128 (2 chunks of 64).
// smem: 8 Q/K tiles x 8KB = 64KB, then mask tile 64x64 fp32 = 16KB. Total 80KB.
__global__ void __launch_bounds__(256, 2) score_hmma(const float* __restrict__ mask)
{
    extern __shared__ char smem[];
    uint32_t sbase = smem_to_u32(smem);
    float* mtile = reinterpret_cast<float*>(smem + 65536);

    const int tid = threadIdx.x, lane = tid & 31, wid = tid >> 5;
    const int wm = wid & 1, wn = wid >> 1;
    int bh = blockIdx.y;
    int b = bh >> 4, h = bh & 15, kv = h >> 2;
    int s0 = blockIdx.x * 64;
    (void)h;

    // Q/K tiles
#pragma unroll
    for (int it = 0; it < 2; ++it) {
        int idx = tid + it * 256;
        int r = idx >> 3, ch = idx & 7;
        uint32_t so = swz((uint32_t)(r * 128 + ch * 16));
        size_t qoff = (size_t)(bh * 64 + r) * HDIM;
        size_t koff = (size_t)((b * NKV + kv) * STOT + s0 + r) * HDIM;
#pragma unroll
        for (int c = 0; c < 2; ++c) {
            CP_ASYNC16(sbase + (0 + c) * 8192 + so, g_qh + qoff + c * 64 + ch * 8);
            CP_ASYNC16(sbase + (2 + c) * 8192 + so, g_ql + qoff + c * 64 + ch * 8);
            CP_ASYNC16(sbase + (4 + c) * 8192 + so, g_Kh + koff + c * 64 + ch * 8);
            CP_ASYNC16(sbase + (6 + c) * 8192 + so, g_Kl + koff + c * 64 + ch * 8);
        }
    }
    // mask tile: 64 q-rows x 64 s-cols fp32 (rows 1024+q of the 1088-row mask)
#pragma unroll
    for (int it = 0; it < 4; ++it) {
        int idx = tid + it * 256;         // 0..1023 = 64 rows x 16 chunks of 16B
        int q = idx >> 4, c16 = idx & 15;
        const float* src = mask + (size_t)b * (1088 * 1344) + (size_t)(1024 + q) * 1344
                         + s0 + c16 * 4;
        CP_ASYNC16(sbase + 65536 + (uint32_t)(q * 256 + c16 * 16), src);
    }
    CP_COMMIT();
    CP_WAIT(0);
    __syncthreads();

    float acc[2][2][4];
#pragma unroll
    for (int i = 0; i < 2; ++i)
#pragma unroll
        for (int j = 0; j < 2; ++j)
#pragma unroll
            for (int k = 0; k < 4; ++k) acc[i][j][k] = 0.f;

    const uint32_t aRow = wm * 32 + (lane & 15);
    const uint32_t aKof = (lane >> 4) * 8;
    const uint32_t bRow = wn * 16 + ((lane >> 4) * 8) + (lane & 7);
    const uint32_t bKof = ((lane >> 3) & 1) * 8;

#pragma unroll
    for (int c = 0; c < 2; ++c) {
        uint32_t tqh = sbase + (0 + c) * 8192, tql = sbase + (2 + c) * 8192;
        uint32_t tkh = sbase + (4 + c) * 8192, tkl = sbase + (6 + c) * 8192;
#pragma unroll
        for (int ks = 0; ks < 4; ++ks) {
            uint32_t ahi[2][4], alo[2][4];
#pragma unroll
            for (int mt = 0; mt < 2; ++mt) {
                uint32_t off = swz((aRow + mt * 16) * 128 + (ks * 16 + aKof) * 2);
                ldsm_x4(ahi[mt], tqh + off);
                ldsm_x4(alo[mt], tql + off);
            }
            uint32_t bh4[4], bl4[4];
            {
                uint32_t off = swz(bRow * 128 + (ks * 16 + bKof) * 2);
                ldsm_x4(bh4, tkh + off);
                ldsm_x4(bl4, tkl + off);
            }
#pragma unroll
            for (int mt = 0; mt < 2; ++mt)
#pragma unroll
                for (int nt = 0; nt < 2; ++nt) {
                    mma_bf16(acc[mt][nt], ahi[mt], &bh4[nt * 2]);
                    mma_bf16(acc[mt][nt], ahi[mt], &bl4[nt * 2]);
                    mma_bf16(acc[mt][nt], alo[mt], &bh4[nt * 2]);
                }
        }
    }

    const float scale = 0.08838834764831845f;
#pragma unroll
    for (int mt = 0; mt < 2; ++mt)
#pragma unroll
        for (int nt = 0; nt < 2; ++nt)
#pragma unroll
            for (int e = 0; e < 4; ++e) {
                int q = wm * 32 + mt * 16 + (lane >> 2) + (e >> 1) * 8;
                int sl = wn * 16 + nt * 8 + 2 * (lane & 3) + (e & 1);
                float v = acc[mt][nt][e] * scale;
                v = fast_tanh(v * 0.02f) * 50.0f + mtile[q * 64 + sl];
                g_scores[(size_t)(bh * 64 + q) * STOT + s0 + sl] = v;
            }
}

// ---------------- HMMA P @ V (validated) ----------------
__global__ void __launch_bounds__(256) pv_hmma()
{
    extern __shared__ char smem[];
    uint32_t sbase = smem_to_u32(smem);

    const int tid = threadIdx.x, lane = tid & 31, wid = tid >> 5;
    const int wm = wid & 1, wn = wid >> 1;
    int bh = blockIdx.x;
    int b = bh >> 4, h = bh & 15, kv = h >> 2;
    int kc0 = blockIdx.y * 192;

    size_t prow0 = (size_t)bh * 64;
    size_t vrow0 = (size_t)(b * NKV + kv) * HDIM;

    auto load_sub = [&](int stage, int kc) {
        uint32_t stb = sbase + stage * 49152;
#pragma unroll
        for (int it = 0; it < 2; ++it) {
            int idx = tid + it * 256;
            int r = idx >> 3, ch = idx & 7;
            uint32_t so = swz((uint32_t)(r * 128 + ch * 16));
            CP_ASYNC16(stb + so,        g_Ph + (prow0 + r) * STOT + kc + ch * 8);
            CP_ASYNC16(stb + 8192 + so, g_Pl + (prow0 + r) * STOT + kc + ch * 8);
        }
#pragma unroll
        for (int it = 0; it < 4; ++it) {
            int idx = tid + it * 256;
            int r = idx >> 3, ch = idx & 7;
            uint32_t so = swz((uint32_t)(r * 128 + ch * 16));
            CP_ASYNC16(stb + 16384 + so, g_Vth + (vrow0 + r) * STOT + kc + ch * 8);
            CP_ASYNC16(stb + 32768 + so, g_Vtl + (vrow0 + r) * STOT + kc + ch * 8);
        }
    };

    float acc[2][4][4];
#pragma unroll
    for (int i = 0; i < 2; ++i)
#pragma unroll
        for (int j = 0; j < 4; ++j)
#pragma unroll
            for (int k = 0; k < 4; ++k) acc[i][j][k] = 0.f;

    load_sub(0, kc0);
    CP_COMMIT();

    const uint32_t aRow = wm * 32 + (lane & 15);
    const uint32_t aKof = (lane >> 4) * 8;
    const uint32_t bRow = wn * 32 + ((lane >> 4) * 8) + (lane & 7);
    const uint32_t bKof = ((lane >> 3) & 1) * 8;

    for (int sub = 0; sub < 3; ++sub) {
        if (sub + 1 < 3) { load_sub((sub + 1) & 1, kc0 + (sub + 1) * 64); CP_COMMIT(); CP_WAIT(1); }
        else             { CP_WAIT(0); }
        __syncthreads();

        uint32_t st = sbase + (sub & 1) * 49152;
        uint32_t tph = st, tpl = st + 8192, tvh = st + 16384, tvl = st + 32768;

#pragma unroll
        for (int ks = 0; ks < 4; ++ks) {
            uint32_t ahi[2][4], alo[2][4];
#pragma unroll
            for (int mt = 0; mt < 2; ++mt) {
                uint32_t off = swz((aRow + mt * 16) * 128 + (ks * 16 + aKof) * 2);
                ldsm_x4(ahi[mt], tph + off);
                ldsm_x4(alo[mt], tpl + off);
            }
            uint32_t bhi[2][4], blo[2][4];
#pragma unroll
            for (int g = 0; g < 2; ++g) {
                uint32_t off = swz((bRow + g * 16) * 128 + (ks * 16 + bKof) * 2);
                ldsm_x4(bhi[g], tvh + off);
                ldsm_x4(blo[g], tvl + off);
            }
#pragma unroll
            for (int mt = 0; mt < 2; ++mt)
#pragma unroll
                for (int nt = 0; nt < 4; ++nt) {
                    const uint32_t* bh4 = &bhi[nt >> 1][(nt & 1) * 2];
                    const uint32_t* bl4 = &blo[nt >> 1][(nt & 1) * 2];
                    mma_bf16(acc[mt][nt], ahi[mt], bh4);
                    mma_bf16(acc[mt][nt], ahi[mt], bl4);
                    mma_bf16(acc[mt][nt], alo[mt], bh4);
                }
        }
        __syncthreads();
    }

#pragma unroll
    for (int mt = 0; mt < 2; ++mt)
#pragma unroll
        for (int nt = 0; nt < 4; ++nt)
#pragma unroll
            for (int e = 0; e < 4; ++e) {
                int q = wm * 32 + mt * 16 + (lane >> 2) + (e >> 1) * 8;
                int d = wn * 32 + nt * 8 + 2 * (lane & 3) + (e & 1);
                atomicAdd(&g_attn[(size_t)(b * SQA + q) * (NH * HDIM) + h * HDIM + d],
                          acc[mt][nt][e]);
            }
}

// ---------------- conversion helpers ----------------
__device__ __forceinline__ void convA_elem(const float4* x, __nv_bfloat162* hi,
                                           __nv_bfloat162* lo, int i)
{
    float4 v = x[i];
    __nv_bfloat16 h0, h1, h2, h3, l0, l1, l2, l3;
    split_bf16(v.x, h0, l0); split_bf16(v.y, h1, l1);
    split_bf16(v.z, h2, l2); split_bf16(v.w, h3, l3);
    hi[i*2+0] = __halves2bfloat162(h0, h1);
    hi[i*2+1] = __halves2bfloat162(h2, h3);
    lo[i*2+0] = __halves2bfloat162(l0, l1);
    lo[i*2+1] = __halves2bfloat162(l2, l3);
}

__device__ __forceinline__ void wt_tile(const float* __restrict__ W,
                                        __nv_bfloat16* bhi, __nv_bfloat16* blo,
                                        int Nd, int k0, int n0, int tx, int ty,
                                        float t[32][33])
{
#pragma unroll
    for (int i = 0; i < 4; ++i)
        t[ty + i*8][tx] = W[(size_t)(k0 + ty + i*8)*Nd + n0 + tx];
    __syncthreads();
#pragma unroll
    for (int i = 0; i < 4; ++i) {
        int n = ty + i*8;
        float v = t[tx][n];
        __nv_bfloat16 h, l; split_bf16(v, h, l);
        size_t o = (size_t)(n0 + n)*2048 + k0 + tx;
        bhi[o] = h; blo[o] = l;
    }
}

// ================= prep1 (validated round 13) =====
#define PREP1_BLOCKS (1024 + 8192 + 512 + 12288)
__global__ void __launch_bounds__(256) prep1_kernel(
    float* out, const float* __restrict__ kc, const float* __restrict__ vc,
    const float* __restrict__ h_vlm, const float* __restrict__ h_act,
    const float* Wkv, const float* Wvv, const float* Wq,
    const float* Wka, const float* Wva, const float* Wo)
{
    __shared__ float t[32][33];
    int bid = blockIdx.x;

    if (bid < 1024) {
        int tid = bid * 256 + threadIdx.x;
        const int stride = 1024 * 256;
        const int nq = BB*NH*SQA*HDIM;
        const int na = BB*SQA*NH*HDIM;
        const int no = BB*SQA*DMODEL;
        const int nact = BB*NKV*SQA*HDIM;
        const int ncache = BB*NKV*SCACHE*HDIM;
        for (int i = tid; i < nq; i += stride) g_q[i] = 0.f;
        for (int i = tid; i < na; i += stride) g_attn[i] = 0.f;
        for (int i = tid; i < no; i += stride) out[i] = 0.f;
        for (int i = tid; i < nact; i += stride) {
            int d  = i & 127;
            int s  = (i >> 7) & 63;
            int bk = i >> 13;
            int idx = (bk*STOT + (SCACHE + SQV) + s)*HDIM + d;
            g_K[idx] = 0.f;
            g_V[idx] = 0.f;
        }
        for (int i = tid; i < ncache; i += stride) {
            int d  = i & 127;
            int s  = (i >> 7) & 255;
            int bk = i >> 15;
            int dst = (bk*STOT + s)*HDIM + d;
            __nv_bfloat16 h, l; split_bf16(kc[i], h, l);
            g_Kh[dst] = h; g_Kl[dst] = l;     // cache keys NOT roped
            g_V[dst] = vc[i];
        }
    } else if (bid < 9216) {
        int i = (bid - 1024) * 256 + threadIdx.x;
        convA_elem((const float4*)h_vlm, (__nv_bfloat162*)g_hv_hi, (__nv_bfloat162*)g_hv_lo, i);
    } else if (bid < 9728) {
        int i = (bid - 9216) * 256 + threadIdx.x;
        convA_elem((const float4*)h_act, (__nv_bfloat162*)g_ha_hi, (__nv_bfloat162*)g_ha_lo, i);
    } else {
        int bx = bid - 9728;
        int tx = threadIdx.x & 31, ty = threadIdx.x >> 5;
        if (bx < 1024)       { int l = bx;        wt_tile(Wkv, g_wkv_hi, g_wkv_lo,  512, (l>>4)*32, (l&15)*32, tx, ty, t); }
        else if (bx < 2048)  { int l = bx - 1024; wt_tile(Wvv, g_wvv_hi, g_wvv_lo,  512, (l>>4)*32, (l&15)*32, tx, ty, t); }
        else if (bx < 6144)  { int l = bx - 2048; wt_tile(Wq,  g_wq_hi,  g_wq_lo,  2048, (l>>6)*32, (l&63)*32, tx, ty, t); }
        else if (bx < 7168)  { int l = bx - 6144; wt_tile(Wka, g_wka_hi, g_wka_lo,  512, (l>>4)*32, (l&15)*32, tx, ty, t); }
        else if (bx < 8192)  { int l = bx - 7168; wt_tile(Wva, g_wva_hi, g_wva_lo,  512, (l>>4)*32, (l&15)*32, tx, ty, t); }
        else                 { int l = bx - 8192; wt_tile(Wo,  g_wo_hi,  g_wo_lo,  2048, (l>>6)*32, (l&63)*32, tx, ty, t); }
    }
}

// ================= prep2 (validated round 13) =====
#define ROPE_T0 (BB*NKV*SQV*64)
#define ROPE_T1 (BB*NKV*SQA*64)
#define ROPE_T2 (BB*NH*SQA*64)
#define PREP2_BLOCKS (5376 + 2688)
__global__ void __launch_bounds__(256) prep2_kernel(
    const int* __restrict__ pos_vlm, const int* __restrict__ pos_act)
{
    __shared__ float t[32][33];
    int bid = blockIdx.x;

    if (bid < 5376) {
        int idx = bid * 256 + threadIdx.x;
        int which, nh, seqlen, s_off;
        const int* pos;
        if (idx < ROPE_T0) { which = 0; pos = pos_vlm; nh = NKV; seqlen = SQV; s_off = SCACHE; }
        else if (idx < ROPE_T0 + ROPE_T1) {
            idx -= ROPE_T0; which = 0; pos = pos_act; nh = NKV; seqlen = SQA; s_off = SCACHE + SQV;
        }
        else {
            idx -= ROPE_T0 + ROPE_T1; which = 1; pos = pos_act; nh = NH; seqlen = SQA; s_off = 0;
        }

        int i = idx & 63;
        int rest = idx >> 6;
        int s = rest % seqlen; rest /= seqlen;
        int hh = rest % nh;
        int b  = rest / nh;

        const float* X = (which == 0) ? g_K : g_q;
        __nv_bfloat16* Xh = (which == 0) ? g_Kh : g_qh;
        __nv_bfloat16* Xl = (which == 0) ? g_Kl : g_ql;
        int stot = (which == 0) ? STOT : SQA;

        int p = pos[b*seqlen + s];
        float inv = exp2f(-0.20762050593046868f * (float)i);
        float ang = (float)p * inv;
        double ad  = (double)ang;
        double red = ad - rint(ad * 0.15915494309189535) * 6.283185307179586;
        float c  = cosf((float)red);
        float sn = sinf((float)red);

        size_t base = ((size_t)((b*nh + hh)*stot + s_off + s)) * HDIM;
        float x1 = X[base + i], x2 = X[base + 64 + i];
        float r1 = x1*c - x2*sn;
        float r2 = x2*c + x1*sn;
        __nv_bfloat16 h, l;
        split_bf16(r1, h, l); Xh[base + i] = h;       Xl[base + i] = l;
        split_bf16(r2, h, l); Xh[base + 64 + i] = h;  Xl[base + 64 + i] = l;
    } else {
        int l = bid - 5376;
        int d0 = (l & 3) * 32;
        int s0 = ((l >> 2) % 42) * 32;
        int z  = l / 168;
        int tx = threadIdx.x & 31, ty = threadIdx.x >> 5;
        const float* V = g_V + (size_t)z*STOT*HDIM;
#pragma unroll
        for (int i = 0; i < 4; ++i)
            t[ty + i*8][tx] = V[(size_t)(s0 + ty + i*8)*HDIM + d0 + tx];
        __syncthreads();
#pragma unroll
        for (int i = 0; i < 4; ++i) {
            int d = ty + i*8;
            float v = t[tx][d];
            __nv_bfloat16 h, l2; split_bf16(v, h, l2);
            size_t o = (size_t)z*HDIM*STOT + (size_t)(d0 + d)*STOT + s0 + tx;
            g_Vth[o] = h; g_Vtl[o] = l2;
        }
    }
}

// ---------------- attn -> bf16 hi/lo ----------------
__global__ void convAT_kernel()
{
    int i = blockIdx.x*blockDim.x + threadIdx.x;
    if (i >= 256*2048/4) return;
    convA_elem((const float4*)g_attn, (__nv_bfloat162*)g_at_hi, (__nv_bfloat162*)g_at_lo, i);
}

// ---------------- row softmax -> P bf16 hi/lo ----------------
__global__ void softmax_kernel()
{
    int row  = blockIdx.x*4 + (threadIdx.x >> 5);
    int lane = threadIdx.x & 31;
    const float* p = g_scores + (size_t)row * STOT;

    float vals[42];
    float m = -1e30f;
#pragma unroll
    for (int i = 0; i < 42; i++) { vals[i] = p[i*32 + lane]; m = fmaxf(m, vals[i]); }
#pragma unroll
    for (int off = 16; off > 0; off >>= 1) m = fmaxf(m, __shfl_xor_sync(0xffffffffu, m, off));
    float sum = 0.f;
#pragma unroll
    for (int i = 0; i < 42; i++) { vals[i] = __expf(vals[i] - m); sum += vals[i]; }
#pragma unroll
    for (int off = 16; off > 0; off >>= 1) sum += __shfl_xor_sync(0xffffffffu, sum, off);
    float invs = 1.0f / sum;
    __nv_bfloat16* ph = g_Ph + (size_t)row * STOT;
    __nv_bfloat16* pl = g_Pl + (size_t)row * STOT;
#pragma unroll
    for (int i = 0; i < 42; i++) {
        float v = vals[i] * invs;
        __nv_bfloat16 h, l; split_bf16(v, h, l);
        ph[i*32 + lane] = h;
        pl[i*32 + lane] = l;
    }
}

// ---------------- launch ----------------
extern "C" void kernel_launch(void* const* d_in, const int* in_sizes, int n_in,
                              void* d_out, int out_size)
{
    (void)in_sizes; (void)n_in; (void)out_size;
    const float* mask    = (const float*)d_in[0];
    const int*   pos_vlm = (const int*)  d_in[1];
    const int*   pos_act = (const int*)  d_in[2];
    const float* h_vlm   = (const float*)d_in[3];
    const float* h_act   = (const float*)d_in[4];
    const float* k_cache = (const float*)d_in[5];
    const float* v_cache = (const float*)d_in[6];
    // d_in[7] = Wq_vlm: unused (q_vlm rows are discarded by reference)
    const float* Wk_vlm  = (const float*)d_in[8];
    const float* Wv_vlm  = (const float*)d_in[9];
    const float* Wq_act  = (const float*)d_in[10];
    const float* Wk_act  = (const float*)d_in[11];
    const float* Wv_act  = (const float*)d_in[12];
    const float* Wo_act  = (const float*)d_in[13];
    float* out = (float*)d_out;

    cudaFuncSetAttribute(tc_proj,    cudaFuncAttributeMaxDynamicSharedMemorySize, TCG_SMEM_BYTES);
    cudaFuncSetAttribute(tc_wo,      cudaFuncAttributeMaxDynamicSharedMemorySize, TCG_SMEM_BYTES);
    cudaFuncSetAttribute(score_hmma, cudaFuncAttributeMaxDynamicSharedMemorySize, 81920);
    cudaFuncSetAttribute(pv_hmma,    cudaFuncAttributeMaxDynamicSharedMemorySize, 98304);

    // 1. prep1: zero/copy + activation conversions + weight transposes
    prep1_kernel<<<PREP1_BLOCKS, 256>>>(out, k_cache, v_cache, h_vlm, h_act,
                                        Wk_vlm, Wv_vlm, Wq_act, Wk_act, Wv_act, Wo_act);

    // 2. ALL projections (vlm KV + act QKV) in ONE launch
    tc_proj<<<896, 256, TCG_SMEM_BYTES>>>();

    // 3. prep2: RoPE+bf16 conversion + V transpose
    prep2_kernel<<<PREP2_BLOCKS, 256>>>(pos_vlm, pos_act);

    // 4-6. attention on HMMA (score: mask-prefetch + fast tanh)
    score_hmma<<<dim3(21, 64), 256, 81920>>>(mask);
    softmax_kernel<<<1024, 128>>>();
    pv_hmma<<<dim3(64, 7), 256, 98304>>>();

    // 7. attn -> bf16 hi/lo
    convAT_kernel<<<(256*2048/4 + 255)/256, 256>>>();

    // 8. output projection, split-K 4
    tc_wo<<<dim3(16, 4, 4), 256, TCG_SMEM_BYTES>>>(out);
}